// round 11
// baseline (speedup 1.0000x reference)
#include <cuda_runtime.h>
#include <cuda_bf16.h>
#include <cstdint>

// Problem constants: 64 graph-sides x 2048 rows x 128 dim.
#define NG 64
#define LL 2048
#define DD 128

typedef unsigned int u32;

__device__ __forceinline__ u32 s2u(const void* p) {
    u32 a; asm("{ .reg .u64 t; cvta.to.shared.u64 t, %1; cvt.u32.u64 %0, t; }" : "=r"(a) : "l"(p)); return a;
}
// 128x128 bf16 tile, 256B rows, 16B-chunk XOR swizzle (conflict-free ldmatrix).
__device__ __forceinline__ u32 phys(u32 r, u32 c) { return r * 256u + (((c ^ (r & 7u)) << 4)); }

__device__ __forceinline__ void ldm4(u32* r, u32 a) {
    asm volatile("ldmatrix.sync.aligned.m8n8.x4.shared.b16 {%0,%1,%2,%3}, [%4];"
                 : "=r"(r[0]), "=r"(r[1]), "=r"(r[2]), "=r"(r[3]) : "r"(a));
}
__device__ __forceinline__ void ldm4t(u32* r, u32 a) {
    asm volatile("ldmatrix.sync.aligned.m8n8.x4.trans.shared.b16 {%0,%1,%2,%3}, [%4];"
                 : "=r"(r[0]), "=r"(r[1]), "=r"(r[2]), "=r"(r[3]) : "r"(a));
}
__device__ __forceinline__ void mma16816(float* c, const u32* a, u32 b0, u32 b1) {
    asm volatile("mma.sync.aligned.m16n8k16.row.col.f32.bf16.bf16.f32 "
        "{%0,%1,%2,%3}, {%4,%5,%6,%7}, {%8,%9}, {%0,%1,%2,%3};"
        : "+f"(c[0]), "+f"(c[1]), "+f"(c[2]), "+f"(c[3])
        : "r"(a[0]), "r"(a[1]), "r"(a[2]), "r"(a[3]), "r"(b0), "r"(b1));
}

__device__ __forceinline__ u32 pk(float a, float b) {
    __nv_bfloat162 t = __floats2bfloat162_rn(a, b); return *(u32*)&t;
}
__device__ __forceinline__ float2 upk(u32 v) {
    return __bfloat1622float2(*(__nv_bfloat162*)&v);
}

// Scratch (plain row-major in gmem; swizzle applied at smem staging)
__device__ float g_gram_part[NG][2][DD * DD];
__device__ __align__(16) __nv_bfloat16 g_gimgH[NG][DD * DD];
__device__ __align__(16) __nv_bfloat16 g_gimgL[NG][DD * DD];
__device__ __align__(16) __nv_bfloat16 g_w2H[DD * DD];

// ---------------------------------------------------------------------------
// Kernel 1: W2 = mp_w^2, hi image only (consistent-weight perturbation)
// ---------------------------------------------------------------------------
__global__ void w2img_kernel(const float* __restrict__ mp_w) {
    int idx = blockIdx.x * blockDim.x + threadIdx.x;
    if (idx < DD * DD) {
        float w = mp_w[idx];
        g_w2H[idx] = __float2bfloat16(w * w);
    }
}

// ---------------------------------------------------------------------------
// Kernel 2: Gram partials.  CTA = (side, K-half). C = Xh^T (Xh + Xl), 2-term.
// ---------------------------------------------------------------------------
__global__ void __launch_bounds__(256) gram_kernel(const float* __restrict__ feats) {
    extern __shared__ __align__(16) unsigned char sm[];
    unsigned char* SH = sm;
    unsigned char* SL = sm + 32768;
    u32 sSH = s2u(sm), sSL = sSH + 32768;

    int side = blockIdx.x >> 1, half = blockIdx.x & 1;
    int t = threadIdx.x, wid = t >> 5, lane = t & 31;
    const float4* X = (const float4*)(feats + ((size_t)side * LL + (size_t)half * 1024) * DD);

    float acc[16][4];
#pragma unroll
    for (int i = 0; i < 16; i++) { acc[i][0] = acc[i][1] = acc[i][2] = acc[i][3] = 0.f; }

    float4 pv[16];
#pragma unroll
    for (int q = 0; q < 16; q++) pv[q] = X[t + 256 * q];

    int m0 = wid * 16;
    u32 a_radd = (u32)((lane & 7) + ((lane >> 4) & 1) * 8);
    u32 a_c    = (u32)(m0 >> 3) + (u32)((lane >> 3) & 1);
    u32 b_radd = (u32)((lane & 7) + ((lane >> 3) & 1) * 8);
    u32 b_cadd = (u32)(lane >> 4);

    for (int c = 0; c < 8; c++) {
        __syncthreads();     // previous compute done with smem
#pragma unroll
        for (int q = 0; q < 16; q++) {
            u32 r = (u32)(wid + 8 * q);
            u32 off = phys(r, (u32)(lane >> 1)) + (u32)(lane & 1) * 8u;
            float4 v = pv[q];
            u32 h0 = pk(v.x, v.y), h1 = pk(v.z, v.w);
            float2 f0 = upk(h0), f1 = upk(h1);
            u32 l0 = pk(v.x - f0.x, v.y - f0.y), l1 = pk(v.z - f1.x, v.w - f1.y);
            *(uint2*)(SH + off) = make_uint2(h0, h1);
            *(uint2*)(SL + off) = make_uint2(l0, l1);
        }
        __syncthreads();
        if (c < 7) {   // prefetch next chunk; latency overlaps compute
            const float4* Xn = X + (size_t)(c + 1) * 4096;
#pragma unroll
            for (int q = 0; q < 16; q++) pv[q] = Xn[t + 256 * q];
        }
#pragma unroll
        for (int ks = 0; ks < 8; ks++) {
            u32 aH[4];
            u32 ar = (u32)(ks * 16) + a_radd;
            ldm4t(aH, sSH + phys(ar, a_c));
            u32 br = (u32)(ks * 16) + b_radd;
#pragma unroll
            for (int np = 0; np < 8; np++) {
                u32 bH[4], bL[4];
                u32 bc = (u32)(np * 2) + b_cadd;
                ldm4t(bH, sSH + phys(br, bc));
                ldm4t(bL, sSL + phys(br, bc));
                mma16816(acc[2 * np],     aH, bH[0], bH[1]);
                mma16816(acc[2 * np],     aH, bL[0], bL[1]);
                mma16816(acc[2 * np + 1], aH, bH[2], bH[3]);
                mma16816(acc[2 * np + 1], aH, bL[2], bL[3]);
            }
        }
    }
    float* dst = g_gram_part[side][half];
    int r0 = m0 + (lane >> 2);
    int j0 = 2 * (lane & 3);
#pragma unroll
    for (int nt = 0; nt < 16; nt++) {
        int j = j0 + 8 * nt;
        *(float2*)&dst[r0 * DD + j]       = make_float2(acc[nt][0], acc[nt][1]);
        *(float2*)&dst[(r0 + 8) * DD + j] = make_float2(acc[nt][2], acc[nt][3]);
    }
}

// ---------------------------------------------------------------------------
// Kernel 3: reduce partials + split hi/lo
// ---------------------------------------------------------------------------
__global__ void reduce_split_kernel() {
    int idx = blockIdx.x * blockDim.x + threadIdx.x;
    int s = idx >> 14, e = idx & 16383;
    float v = g_gram_part[s][0][e] + g_gram_part[s][1][e];
    __nv_bfloat16 h = __float2bfloat16(v);
    g_gimgH[s][e] = h;
    g_gimgL[s][e] = __float2bfloat16(v - __bfloat162float(h));
}

// ---------------------------------------------------------------------------
// Kernel 4: PERSISTENT fused kernel. CTA = (graph-side, row-half): stages
// G (split) + W2 (hi) ONCE, then loops over 8 row-tiles:
//   stage X -> GEMM1 V=Xh(Gh+Gl) -> E build -> GEMM2 vs W2 -> epilogue.
// smem: XH XL (X / E1 E2), E0H E0L, GH GL (resident), WH (resident) = 224 KB.
// ---------------------------------------------------------------------------
#define FUSED_SMEM (7 * 32768)

__global__ void __launch_bounds__(256) fused_kernel(const float* __restrict__ feats,
                                                    float* __restrict__ out) {
    extern __shared__ __align__(16) unsigned char sm[];
    unsigned char* XH  = sm;
    unsigned char* XL  = sm + 32768;
    unsigned char* E0H = sm + 65536;
    unsigned char* E0L = sm + 98304;
    unsigned char* GH  = sm + 131072;
    unsigned char* GL  = sm + 163840;
    unsigned char* WH  = sm + 196608;
    u32 sXH = s2u(sm), sXL = sXH + 32768;
    u32 sE0H = sXH + 65536, sE0L = sXH + 98304;
    u32 sGH = sXH + 131072, sGL = sXH + 163840;
    u32 sWH = sXH + 196608;

    int g = blockIdx.x >> 1, rh = blockIdx.x & 1;
    int t = threadIdx.x, wid = t >> 5, lane = t & 31;

    // ---- stage resident tiles: G (partner, split) + W2 (hi)
    {
        const uint4* gh = (const uint4*)&g_gimgH[g ^ 1][0];
        const uint4* gl = (const uint4*)&g_gimgL[g ^ 1][0];
        const uint4* wh = (const uint4*)&g_w2H[0];
#pragma unroll
        for (int q = 0; q < 8; q++) {
            int idx = t + 256 * q;
            u32 r = (u32)(idx >> 4), ch = (u32)(idx & 15);
            u32 off = phys(r, ch);
            *(uint4*)(GH + off) = gh[idx];
            *(uint4*)(GL + off) = gl[idx];
            *(uint4*)(WH + off) = wh[idx];
        }
    }

    int m0 = wid * 16;
    u32 aA_r = (u32)m0 + (u32)(lane & 15);
    u32 aA_c = (u32)(lane >> 4);
    u32 bB_radd = (u32)((lane & 7) + (lane >> 4) * 8);
    u32 bB_cadd = (u32)((lane >> 3) & 1);

#pragma unroll 1
    for (int tt = 0; tt < 8; tt++) {
        size_t lbase = (size_t)g * LL + (size_t)(rh * 8 + tt) * 128;

        // ---- stage X (split) ; top-of-loop: prior GEMM2 reads of XH/XL are
        // fenced by the syncthreads at the end of the previous iteration.
        {
            const float4* xs = (const float4*)(feats + lbase * DD);
            float4 v[16];
#pragma unroll
            for (int q = 0; q < 16; q++) v[q] = xs[t + 256 * q];
#pragma unroll
            for (int q = 0; q < 16; q++) {
                int idx = t + 256 * q;
                u32 r = (u32)(idx >> 5);
                u32 ln = (u32)(idx & 31);
                u32 off = phys(r, ln >> 1) + (ln & 1) * 8u;
                u32 h0 = pk(v[q].x, v[q].y), h1 = pk(v[q].z, v[q].w);
                float2 f0 = upk(h0), f1 = upk(h1);
                u32 l0 = pk(v[q].x - f0.x, v[q].y - f0.y), l1 = pk(v[q].z - f1.x, v[q].w - f1.y);
                *(uint2*)(XH + off) = make_uint2(h0, h1);
                *(uint2*)(XL + off) = make_uint2(l0, l1);
            }
        }
        __syncthreads();

        // ---- GEMM1: V = Xh · (Gh + Gl)   (2-term)
        float vac[16][4];
#pragma unroll
        for (int i = 0; i < 16; i++) { vac[i][0] = vac[i][1] = vac[i][2] = vac[i][3] = 0.f; }
#pragma unroll
        for (int ks = 0; ks < 8; ks++) {
            u32 aH[4];
            u32 ac = (u32)(ks * 2) + aA_c;
            ldm4(aH, sXH + phys(aA_r, ac));
            u32 bc = (u32)(ks * 2) + bB_cadd;
#pragma unroll
            for (int np = 0; np < 8; np++) {
                u32 br = (u32)(np * 16) + bB_radd;
                u32 bH[4], bL[4];
                ldm4(bH, sGH + phys(br, bc));
                ldm4(bL, sGL + phys(br, bc));
                mma16816(vac[2 * np],     aH, bH[0], bH[1]);
                mma16816(vac[2 * np],     aH, bL[0], bL[1]);
                mma16816(vac[2 * np + 1], aH, bH[2], bH[3]);
                mma16816(vac[2 * np + 1], aH, bL[2], bL[3]);
            }
        }
        __syncthreads();   // all GEMM1 reads of XH done before E overwrites

        // ---- E build: thread-owned read-modify-write positions.
        // E0 (x*v) split -> E0H/E0L ; E1 (x^2) -> XH ; E2 (v^2) -> XL.
        {
            u32 r = (u32)m0 + (u32)(lane >> 2);
            u32 sub = 4u * (u32)(lane & 3);
#pragma unroll
            for (int nt = 0; nt < 16; nt++) {
                u32 offA = phys(r, (u32)nt) + sub;
                u32 offB = phys(r + 8, (u32)nt) + sub;
                {
                    float2 xh = upk(*(u32*)(XH + offA));
                    float2 xl = upk(*(u32*)(XL + offA));
                    float x0 = xh.x + xl.x, x1 = xh.y + xl.y;
                    float v0 = vac[nt][0], v1 = vac[nt][1];
                    float e0 = x0 * v0, e1 = x1 * v1;
                    u32 h = pk(e0, e1); float2 hf = upk(h);
                    *(u32*)(E0H + offA) = h;
                    *(u32*)(E0L + offA) = pk(e0 - hf.x, e1 - hf.y);
                    *(u32*)(XH + offA) = pk(x0 * x0, x1 * x1);
                    *(u32*)(XL + offA) = pk(v0 * v0, v1 * v1);
                }
                {
                    float2 xh = upk(*(u32*)(XH + offB));
                    float2 xl = upk(*(u32*)(XL + offB));
                    float x0 = xh.x + xl.x, x1 = xh.y + xl.y;
                    float v0 = vac[nt][2], v1 = vac[nt][3];
                    float e0 = x0 * v0, e1 = x1 * v1;
                    u32 h = pk(e0, e1); float2 hf = upk(h);
                    *(u32*)(E0H + offB) = h;
                    *(u32*)(E0L + offB) = pk(e0 - hf.x, e1 - hf.y);
                    *(u32*)(XH + offB) = pk(x0 * x0, x1 * x1);
                    *(u32*)(XL + offB) = pk(v0 * v0, v1 * v1);
                }
            }
        }
        __syncthreads();

        // ---- GEMM2 (+fused epilogue), W2 hi-only; num 2-term, n1/n2 1-term
        float* outp = out + lbase * DD;
        int r0 = m0 + (lane >> 2);
#pragma unroll 1
        for (int nh = 0; nh < 2; nh++) {
            float aN[8][4], a1[8][4], a2[8][4];
#pragma unroll
            for (int i = 0; i < 8; i++) {
                aN[i][0] = aN[i][1] = aN[i][2] = aN[i][3] = 0.f;
                a1[i][0] = a1[i][1] = a1[i][2] = a1[i][3] = 0.f;
                a2[i][0] = a2[i][1] = a2[i][2] = a2[i][3] = 0.f;
            }
#pragma unroll
            for (int ks = 0; ks < 8; ks++) {
                u32 ac = (u32)(ks * 2) + aA_c;
                u32 aoff = phys(aA_r, ac);
                u32 e0h[4], e0l[4], e1f[4], e2f[4];
                ldm4(e0h, sE0H + aoff);
                ldm4(e0l, sE0L + aoff);
                ldm4(e1f, sXH + aoff);
                ldm4(e2f, sXL + aoff);
                u32 bc = (u32)(ks * 2) + bB_cadd;
#pragma unroll
                for (int np = 0; np < 4; np++) {
                    u32 br = (u32)(nh * 64 + np * 16) + bB_radd;
                    u32 wh[4];
                    ldm4(wh, sWH + phys(br, bc));
                    mma16816(aN[2 * np], e0h, wh[0], wh[1]);
                    mma16816(aN[2 * np], e0l, wh[0], wh[1]);
                    mma16816(a1[2 * np], e1f, wh[0], wh[1]);
                    mma16816(a2[2 * np], e2f, wh[0], wh[1]);
                    mma16816(aN[2 * np + 1], e0h, wh[2], wh[3]);
                    mma16816(aN[2 * np + 1], e0l, wh[2], wh[3]);
                    mma16816(a1[2 * np + 1], e1f, wh[2], wh[3]);
                    mma16816(a2[2 * np + 1], e2f, wh[2], wh[3]);
                }
            }
#pragma unroll
            for (int nt = 0; nt < 8; nt++) {
                int p0 = nh * 64 + nt * 8 + 2 * (lane & 3);
                float d0 = fmaxf(sqrtf(a1[nt][0] * a2[nt][0]), 1e-8f);
                float d1 = fmaxf(sqrtf(a1[nt][1] * a2[nt][1]), 1e-8f);
                float d2 = fmaxf(sqrtf(a1[nt][2] * a2[nt][2]), 1e-8f);
                float d3 = fmaxf(sqrtf(a1[nt][3] * a2[nt][3]), 1e-8f);
                *(float2*)&outp[(size_t)r0 * DD + p0] =
                    make_float2(__fdividef(aN[nt][0], d0), __fdividef(aN[nt][1], d1));
                *(float2*)&outp[(size_t)(r0 + 8) * DD + p0] =
                    make_float2(__fdividef(aN[nt][2], d2), __fdividef(aN[nt][3], d3));
            }
        }
        __syncthreads();   // GEMM2 reads done before next tile's X staging
    }
}

// ---------------------------------------------------------------------------
extern "C" void kernel_launch(void* const* d_in, const int* in_sizes, int n_in,
                              void* d_out, int out_size) {
    const float* feats = (const float*)d_in[0];
    const float* mp_w  = (const float*)d_in[1];
    float* out = (float*)d_out;

    cudaFuncSetAttribute(gram_kernel,  cudaFuncAttributeMaxDynamicSharedMemorySize, 65536);
    cudaFuncSetAttribute(fused_kernel, cudaFuncAttributeMaxDynamicSharedMemorySize, FUSED_SMEM);

    w2img_kernel<<<64, 256>>>(mp_w);
    gram_kernel<<<NG * 2, 256, 65536>>>(feats);
    reduce_split_kernel<<<(NG * DD * DD) / 256, 256>>>();
    fused_kernel<<<NG * 2, 256, FUSED_SMEM>>>(feats, out);
}

// round 12
// speedup vs baseline: 1.2219x; 1.2219x over previous
#include <cuda_runtime.h>
#include <cuda_bf16.h>
#include <cstdint>

// Problem constants: 64 graph-sides x 2048 rows x 128 dim.
#define NG 64
#define LL 2048
#define DD 128

typedef unsigned int u32;

__device__ __forceinline__ u32 s2u(const void* p) {
    u32 a; asm("{ .reg .u64 t; cvta.to.shared.u64 t, %1; cvt.u32.u64 %0, t; }" : "=r"(a) : "l"(p)); return a;
}
// 128x128 bf16 tile, 256B rows, 16B-chunk XOR swizzle (conflict-free ldmatrix).
__device__ __forceinline__ u32 phys(u32 r, u32 c) { return r * 256u + (((c ^ (r & 7u)) << 4)); }

__device__ __forceinline__ void ldm4(u32* r, u32 a) {
    asm volatile("ldmatrix.sync.aligned.m8n8.x4.shared.b16 {%0,%1,%2,%3}, [%4];"
                 : "=r"(r[0]), "=r"(r[1]), "=r"(r[2]), "=r"(r[3]) : "r"(a));
}
__device__ __forceinline__ void ldm4t(u32* r, u32 a) {
    asm volatile("ldmatrix.sync.aligned.m8n8.x4.trans.shared.b16 {%0,%1,%2,%3}, [%4];"
                 : "=r"(r[0]), "=r"(r[1]), "=r"(r[2]), "=r"(r[3]) : "r"(a));
}
__device__ __forceinline__ void mma16816(float* c, const u32* a, u32 b0, u32 b1) {
    asm volatile("mma.sync.aligned.m16n8k16.row.col.f32.bf16.bf16.f32 "
        "{%0,%1,%2,%3}, {%4,%5,%6,%7}, {%8,%9}, {%0,%1,%2,%3};"
        : "+f"(c[0]), "+f"(c[1]), "+f"(c[2]), "+f"(c[3])
        : "r"(a[0]), "r"(a[1]), "r"(a[2]), "r"(a[3]), "r"(b0), "r"(b1));
}

__device__ __forceinline__ u32 pk(float a, float b) {
    __nv_bfloat162 t = __floats2bfloat162_rn(a, b); return *(u32*)&t;
}
__device__ __forceinline__ float2 upk(u32 v) {
    return __bfloat1622float2(*(__nv_bfloat162*)&v);
}

// Scratch (plain row-major in gmem; swizzle applied at smem staging)
__device__ float g_gram_part[NG][2][DD * DD];
__device__ __align__(16) __nv_bfloat16 g_gimgH[NG][DD * DD];
__device__ __align__(16) __nv_bfloat16 g_gimgL[NG][DD * DD];
__device__ __align__(16) __nv_bfloat16 g_w2H[DD * DD];

// ---------------------------------------------------------------------------
// Kernel 1: W2 = mp_w^2, hi image only (consistent-weight perturbation)
// ---------------------------------------------------------------------------
__global__ void w2img_kernel(const float* __restrict__ mp_w) {
    int idx = blockIdx.x * blockDim.x + threadIdx.x;
    if (idx < DD * DD) {
        float w = mp_w[idx];
        g_w2H[idx] = __float2bfloat16(w * w);
    }
}

// ---------------------------------------------------------------------------
// Kernel 2: Gram partials.  CTA = (side, K-half), 512 threads / 16 warps.
// warp = (m-tile, n-half).  C = Xh^T (Xh + Xl), 2-term.
// ---------------------------------------------------------------------------
__global__ void __launch_bounds__(512) gram_kernel(const float* __restrict__ feats) {
    extern __shared__ __align__(16) unsigned char sm[];
    unsigned char* SH = sm;
    unsigned char* SL = sm + 32768;
    u32 sSH = s2u(sm), sSL = sSH + 32768;

    int side = blockIdx.x >> 1, half = blockIdx.x & 1;
    int t = threadIdx.x, wid = t >> 5, lane = t & 31;
    const float4* X = (const float4*)(feats + ((size_t)side * LL + (size_t)half * 1024) * DD);

    int mw = wid >> 1, nhf = wid & 1;
    int m0 = mw * 16;

    float acc[8][4];
#pragma unroll
    for (int i = 0; i < 8; i++) { acc[i][0] = acc[i][1] = acc[i][2] = acc[i][3] = 0.f; }

    float4 pv[8];
#pragma unroll
    for (int q = 0; q < 8; q++) pv[q] = X[t + 512 * q];

    u32 a_radd = (u32)((lane & 7) + ((lane >> 4) & 1) * 8);
    u32 a_c    = (u32)(mw * 2) + (u32)((lane >> 3) & 1);
    u32 b_radd = (u32)((lane & 7) + ((lane >> 3) & 1) * 8);
    u32 b_cadd = (u32)(lane >> 4);

    for (int c = 0; c < 8; c++) {
        __syncthreads();     // previous compute done with smem
#pragma unroll
        for (int q = 0; q < 8; q++) {
            u32 r = (u32)(wid + 16 * q);
            u32 off = phys(r, (u32)(lane >> 1)) + (u32)(lane & 1) * 8u;
            float4 v = pv[q];
            u32 h0 = pk(v.x, v.y), h1 = pk(v.z, v.w);
            float2 f0 = upk(h0), f1 = upk(h1);
            u32 l0 = pk(v.x - f0.x, v.y - f0.y), l1 = pk(v.z - f1.x, v.w - f1.y);
            *(uint2*)(SH + off) = make_uint2(h0, h1);
            *(uint2*)(SL + off) = make_uint2(l0, l1);
        }
        __syncthreads();
        if (c < 7) {   // prefetch next chunk; latency overlaps compute
            const float4* Xn = X + (size_t)(c + 1) * 4096;
#pragma unroll
            for (int q = 0; q < 8; q++) pv[q] = Xn[t + 512 * q];
        }
#pragma unroll
        for (int ks = 0; ks < 8; ks++) {
            u32 aH[4];
            u32 ar = (u32)(ks * 16) + a_radd;
            ldm4t(aH, sSH + phys(ar, a_c));
            u32 br = (u32)(ks * 16) + b_radd;
#pragma unroll
            for (int np = 0; np < 4; np++) {
                u32 bH[4], bL[4];
                u32 bc = (u32)(nhf * 8 + np * 2) + b_cadd;
                ldm4t(bH, sSH + phys(br, bc));
                ldm4t(bL, sSL + phys(br, bc));
                mma16816(acc[2 * np],     aH, bH[0], bH[1]);
                mma16816(acc[2 * np],     aH, bL[0], bL[1]);
                mma16816(acc[2 * np + 1], aH, bH[2], bH[3]);
                mma16816(acc[2 * np + 1], aH, bL[2], bL[3]);
            }
        }
    }
    float* dst = g_gram_part[side][half];
    int r0 = m0 + (lane >> 2);
    int j0 = nhf * 64 + 2 * (lane & 3);
#pragma unroll
    for (int nt = 0; nt < 8; nt++) {
        int j = j0 + 8 * nt;
        *(float2*)&dst[r0 * DD + j]       = make_float2(acc[nt][0], acc[nt][1]);
        *(float2*)&dst[(r0 + 8) * DD + j] = make_float2(acc[nt][2], acc[nt][3]);
    }
}

// ---------------------------------------------------------------------------
// Kernel 3: reduce partials + split hi/lo
// ---------------------------------------------------------------------------
__global__ void reduce_split_kernel() {
    int idx = blockIdx.x * blockDim.x + threadIdx.x;
    int s = idx >> 14, e = idx & 16383;
    float v = g_gram_part[s][0][e] + g_gram_part[s][1][e];
    __nv_bfloat16 h = __float2bfloat16(v);
    g_gimgH[s][e] = h;
    g_gimgL[s][e] = __float2bfloat16(v - __bfloat162float(h));
}

// ---------------------------------------------------------------------------
// Kernel 4: fused  V2 = Xh·G_partner -> E build -> match GEMMs.  512 threads,
// 16 warps, warp = (m-tile mw, n-half nhf).  CTA = one 128-row tile.
// smem: XH XL (X, later E1=x^2 / E2=v^2), BH BL (G, later E0 hi/lo), WH.
// ---------------------------------------------------------------------------
#define FUSED_SMEM (5 * 32768)

__global__ void __launch_bounds__(512) fused_kernel(const float* __restrict__ feats,
                                                    float* __restrict__ out) {
    extern __shared__ __align__(16) unsigned char sm[];
    unsigned char* XH = sm;
    unsigned char* XL = sm + 32768;
    unsigned char* BH = sm + 65536;
    unsigned char* BL = sm + 98304;
    unsigned char* WH = sm + 131072;
    u32 sXH = s2u(sm), sXL = sXH + 32768;
    u32 sBH = sXH + 65536, sBL = sXH + 98304;
    u32 sWH = sXH + 131072;

    int blk = blockIdx.x, g = blk >> 4, tile = blk & 15;
    int t = threadIdx.x, wid = t >> 5, lane = t & 31;
    size_t lbase = (size_t)g * LL + (size_t)tile * 128;

    int mw = wid >> 1, nhf = wid & 1;
    int m0 = mw * 16;

    // ---- stage: X (split), G (partner, split), W2 (hi only)
    {
        const float4* xs = (const float4*)(feats + lbase * DD);
#pragma unroll
        for (int q = 0; q < 8; q++) {
            int idx = t + 512 * q;
            u32 r = (u32)(idx >> 5);
            u32 ln = (u32)(idx & 31);
            u32 off = phys(r, ln >> 1) + (ln & 1) * 8u;
            float4 v = xs[idx];
            u32 h0 = pk(v.x, v.y), h1 = pk(v.z, v.w);
            float2 f0 = upk(h0), f1 = upk(h1);
            u32 l0 = pk(v.x - f0.x, v.y - f0.y), l1 = pk(v.z - f1.x, v.w - f1.y);
            *(uint2*)(XH + off) = make_uint2(h0, h1);
            *(uint2*)(XL + off) = make_uint2(l0, l1);
        }
        const uint4* gh = (const uint4*)&g_gimgH[g ^ 1][0];
        const uint4* gl = (const uint4*)&g_gimgL[g ^ 1][0];
        const uint4* wh = (const uint4*)&g_w2H[0];
#pragma unroll
        for (int q = 0; q < 4; q++) {
            int idx = t + 512 * q;
            u32 r = (u32)(idx >> 4), ch = (u32)(idx & 15);
            u32 off = phys(r, ch);
            *(uint4*)(BH + off) = gh[idx];
            *(uint4*)(BL + off) = gl[idx];
            *(uint4*)(WH + off) = wh[idx];
        }
    }
    __syncthreads();

    u32 aA_r = (u32)m0 + (u32)(lane & 15);
    u32 aA_c = (u32)(lane >> 4);
    u32 bB_radd = (u32)((lane & 7) + (lane >> 4) * 8);
    u32 bB_cadd = (u32)((lane >> 3) & 1);

    // ---- GEMM1: V = Xh · (Gh + Gl)   (2-term); warp covers n in [nhf*64, +64)
    float vac[8][4];
#pragma unroll
    for (int i = 0; i < 8; i++) { vac[i][0] = vac[i][1] = vac[i][2] = vac[i][3] = 0.f; }
#pragma unroll
    for (int ks = 0; ks < 8; ks++) {
        u32 aH[4];
        u32 ac = (u32)(ks * 2) + aA_c;
        ldm4(aH, sXH + phys(aA_r, ac));
        u32 bc = (u32)(ks * 2) + bB_cadd;
#pragma unroll
        for (int np = 0; np < 4; np++) {
            u32 br = (u32)(nhf * 64 + np * 16) + bB_radd;
            u32 bH[4], bL[4];
            ldm4(bH, sBH + phys(br, bc));
            ldm4(bL, sBL + phys(br, bc));
            mma16816(vac[2 * np],     aH, bH[0], bH[1]);
            mma16816(vac[2 * np],     aH, bL[0], bL[1]);
            mma16816(vac[2 * np + 1], aH, bH[2], bH[3]);
            mma16816(vac[2 * np + 1], aH, bL[2], bL[3]);
        }
    }
    __syncthreads();   // all GEMM1 smem reads complete before E overwrites

    // ---- E build: each thread owns exactly the elements it reads & writes
    // (rows of its m-tile, cols of its n-half).
    // E0 (x*v) split -> BH/BL ; E1 (x^2) -> XH ; E2 (v^2) -> XL.
    {
        u32 r = (u32)m0 + (u32)(lane >> 2);
        u32 sub = 4u * (u32)(lane & 3);
#pragma unroll
        for (int nt = 0; nt < 8; nt++) {
            u32 chunk = (u32)(nhf * 8 + nt);
            u32 offA = phys(r, chunk) + sub;          // (r+8)&7 == r&7 -> same xor
            u32 offB = phys(r + 8, chunk) + sub;
            {
                float2 xh = upk(*(u32*)(XH + offA));
                float2 xl = upk(*(u32*)(XL + offA));
                float x0 = xh.x + xl.x, x1 = xh.y + xl.y;
                float v0 = vac[nt][0], v1 = vac[nt][1];
                float e0 = x0 * v0, e1 = x1 * v1;
                u32 h = pk(e0, e1); float2 hf = upk(h);
                *(u32*)(BH + offA) = h;
                *(u32*)(BL + offA) = pk(e0 - hf.x, e1 - hf.y);
                *(u32*)(XH + offA) = pk(x0 * x0, x1 * x1);
                *(u32*)(XL + offA) = pk(v0 * v0, v1 * v1);
            }
            {
                float2 xh = upk(*(u32*)(XH + offB));
                float2 xl = upk(*(u32*)(XL + offB));
                float x0 = xh.x + xl.x, x1 = xh.y + xl.y;
                float v0 = vac[nt][2], v1 = vac[nt][3];
                float e0 = x0 * v0, e1 = x1 * v1;
                u32 h = pk(e0, e1); float2 hf = upk(h);
                *(u32*)(BH + offB) = h;
                *(u32*)(BL + offB) = pk(e0 - hf.x, e1 - hf.y);
                *(u32*)(XH + offB) = pk(x0 * x0, x1 * x1);
                *(u32*)(XL + offB) = pk(v0 * v0, v1 * v1);
            }
        }
    }
    __syncthreads();

    // ---- GEMM2 (+fused epilogue): warp covers p in [nhf*64, +64), two
    // passes of 32 perspectives to cap register pressure.
    float* outp = out + lbase * DD;
    int r0 = m0 + (lane >> 2);
#pragma unroll 1
    for (int pp = 0; pp < 2; pp++) {
        float aN[4][4], a1[4][4], a2[4][4];
#pragma unroll
        for (int i = 0; i < 4; i++) {
            aN[i][0] = aN[i][1] = aN[i][2] = aN[i][3] = 0.f;
            a1[i][0] = a1[i][1] = a1[i][2] = a1[i][3] = 0.f;
            a2[i][0] = a2[i][1] = a2[i][2] = a2[i][3] = 0.f;
        }
#pragma unroll
        for (int ks = 0; ks < 8; ks++) {
            u32 ac = (u32)(ks * 2) + aA_c;
            u32 aoff = phys(aA_r, ac);
            u32 e0h[4], e0l[4], e1f[4], e2f[4];
            ldm4(e0h, sBH + aoff);
            ldm4(e0l, sBL + aoff);
            ldm4(e1f, sXH + aoff);
            ldm4(e2f, sXL + aoff);
            u32 bc = (u32)(ks * 2) + bB_cadd;
#pragma unroll
            for (int np = 0; np < 2; np++) {
                u32 br = (u32)(nhf * 64 + pp * 32 + np * 16) + bB_radd;
                u32 wh[4];
                ldm4(wh, sWH + phys(br, bc));
                mma16816(aN[2 * np], e0h, wh[0], wh[1]);
                mma16816(aN[2 * np], e0l, wh[0], wh[1]);
                mma16816(a1[2 * np], e1f, wh[0], wh[1]);
                mma16816(a2[2 * np], e2f, wh[0], wh[1]);
                mma16816(aN[2 * np + 1], e0h, wh[2], wh[3]);
                mma16816(aN[2 * np + 1], e0l, wh[2], wh[3]);
                mma16816(a1[2 * np + 1], e1f, wh[2], wh[3]);
                mma16816(a2[2 * np + 1], e2f, wh[2], wh[3]);
            }
        }
#pragma unroll
        for (int nt = 0; nt < 4; nt++) {
            int p0 = nhf * 64 + pp * 32 + nt * 8 + 2 * (lane & 3);
            float d0 = fmaxf(sqrtf(a1[nt][0] * a2[nt][0]), 1e-8f);
            float d1 = fmaxf(sqrtf(a1[nt][1] * a2[nt][1]), 1e-8f);
            float d2 = fmaxf(sqrtf(a1[nt][2] * a2[nt][2]), 1e-8f);
            float d3 = fmaxf(sqrtf(a1[nt][3] * a2[nt][3]), 1e-8f);
            *(float2*)&outp[(size_t)r0 * DD + p0] =
                make_float2(__fdividef(aN[nt][0], d0), __fdividef(aN[nt][1], d1));
            *(float2*)&outp[(size_t)(r0 + 8) * DD + p0] =
                make_float2(__fdividef(aN[nt][2], d2), __fdividef(aN[nt][3], d3));
        }
    }
}

// ---------------------------------------------------------------------------
extern "C" void kernel_launch(void* const* d_in, const int* in_sizes, int n_in,
                              void* d_out, int out_size) {
    const float* feats = (const float*)d_in[0];
    const float* mp_w  = (const float*)d_in[1];
    float* out = (float*)d_out;

    cudaFuncSetAttribute(gram_kernel,  cudaFuncAttributeMaxDynamicSharedMemorySize, 65536);
    cudaFuncSetAttribute(fused_kernel, cudaFuncAttributeMaxDynamicSharedMemorySize, FUSED_SMEM);

    w2img_kernel<<<64, 256>>>(mp_w);
    gram_kernel<<<NG * 2, 512, 65536>>>(feats);
    reduce_split_kernel<<<(NG * DD * DD) / 256, 256>>>();
    fused_kernel<<<NG * (LL / 128), 512, FUSED_SMEM>>>(feats, out);
}

// round 13
// speedup vs baseline: 1.4555x; 1.1912x over previous
#include <cuda_runtime.h>
#include <cuda_bf16.h>
#include <cstdint>

// Problem constants: 64 graph-sides x 2048 rows x 128 dim.
#define NG 64
#define LL 2048
#define DD 128

typedef unsigned int u32;

__device__ __forceinline__ u32 s2u(const void* p) {
    u32 a; asm("{ .reg .u64 t; cvta.to.shared.u64 t, %1; cvt.u32.u64 %0, t; }" : "=r"(a) : "l"(p)); return a;
}
// 128x128 bf16 tile, 256B rows, 16B-chunk XOR swizzle (conflict-free ldmatrix).
__device__ __forceinline__ u32 phys(u32 r, u32 c) { return r * 256u + (((c ^ (r & 7u)) << 4)); }

__device__ __forceinline__ void ldm4(u32* r, u32 a) {
    asm volatile("ldmatrix.sync.aligned.m8n8.x4.shared.b16 {%0,%1,%2,%3}, [%4];"
                 : "=r"(r[0]), "=r"(r[1]), "=r"(r[2]), "=r"(r[3]) : "r"(a));
}
__device__ __forceinline__ void ldm4t(u32* r, u32 a) {
    asm volatile("ldmatrix.sync.aligned.m8n8.x4.trans.shared.b16 {%0,%1,%2,%3}, [%4];"
                 : "=r"(r[0]), "=r"(r[1]), "=r"(r[2]), "=r"(r[3]) : "r"(a));
}
__device__ __forceinline__ void mma16816(float* c, const u32* a, u32 b0, u32 b1) {
    asm volatile("mma.sync.aligned.m16n8k16.row.col.f32.bf16.bf16.f32 "
        "{%0,%1,%2,%3}, {%4,%5,%6,%7}, {%8,%9}, {%0,%1,%2,%3};"
        : "+f"(c[0]), "+f"(c[1]), "+f"(c[2]), "+f"(c[3])
        : "r"(a[0]), "r"(a[1]), "r"(a[2]), "r"(a[3]), "r"(b0), "r"(b1));
}

__device__ __forceinline__ u32 pk(float a, float b) {
    __nv_bfloat162 t = __floats2bfloat162_rn(a, b); return *(u32*)&t;
}
__device__ __forceinline__ float2 upk(u32 v) {
    return __bfloat1622float2(*(__nv_bfloat162*)&v);
}

// Scratch (plain row-major in gmem; swizzle applied at smem staging)
__device__ float g_gram_part[NG][2][DD * DD];
__device__ __align__(16) __nv_bfloat16 g_gimgH[NG][DD * DD];
__device__ __align__(16) __nv_bfloat16 g_w2H[DD * DD];

// ---------------------------------------------------------------------------
// Kernel 1: W2 = mp_w^2, hi image only (consistent-weight perturbation)
// ---------------------------------------------------------------------------
__global__ void w2img_kernel(const float* __restrict__ mp_w) {
    int idx = blockIdx.x * blockDim.x + threadIdx.x;
    if (idx < DD * DD) {
        float w = mp_w[idx];
        g_w2H[idx] = __float2bfloat16(w * w);
    }
}

// ---------------------------------------------------------------------------
// Kernel 2: Gram partials.  CTA = (side, K-half), 512 threads / 16 warps.
// warp = (m-tile, n-half).  C = Xh^T Xh  (1-term: G is bf16-rounded downstream,
// so the lo refinement is below the consumer's noise floor).
// ---------------------------------------------------------------------------
__global__ void __launch_bounds__(512) gram_kernel(const float* __restrict__ feats) {
    extern __shared__ __align__(16) unsigned char sm[];
    unsigned char* SH = sm;
    u32 sSH = s2u(sm);

    int side = blockIdx.x >> 1, half = blockIdx.x & 1;
    int t = threadIdx.x, wid = t >> 5, lane = t & 31;
    const float4* X = (const float4*)(feats + ((size_t)side * LL + (size_t)half * 1024) * DD);

    int mw = wid >> 1, nhf = wid & 1;
    int m0 = mw * 16;

    float acc[8][4];
#pragma unroll
    for (int i = 0; i < 8; i++) { acc[i][0] = acc[i][1] = acc[i][2] = acc[i][3] = 0.f; }

    float4 pv[8];
#pragma unroll
    for (int q = 0; q < 8; q++) pv[q] = X[t + 512 * q];

    u32 a_radd = (u32)((lane & 7) + ((lane >> 4) & 1) * 8);
    u32 a_c    = (u32)(mw * 2) + (u32)((lane >> 3) & 1);
    u32 b_radd = (u32)((lane & 7) + ((lane >> 3) & 1) * 8);
    u32 b_cadd = (u32)(lane >> 4);

    for (int c = 0; c < 8; c++) {
        __syncthreads();     // previous compute done with smem
#pragma unroll
        for (int q = 0; q < 8; q++) {
            u32 r = (u32)(wid + 16 * q);
            u32 off = phys(r, (u32)(lane >> 1)) + (u32)(lane & 1) * 8u;
            float4 v = pv[q];
            *(uint2*)(SH + off) = make_uint2(pk(v.x, v.y), pk(v.z, v.w));
        }
        __syncthreads();
        if (c < 7) {   // prefetch next chunk; latency overlaps compute
            const float4* Xn = X + (size_t)(c + 1) * 4096;
#pragma unroll
            for (int q = 0; q < 8; q++) pv[q] = Xn[t + 512 * q];
        }
#pragma unroll
        for (int ks = 0; ks < 8; ks++) {
            u32 aH[4];
            u32 ar = (u32)(ks * 16) + a_radd;
            ldm4t(aH, sSH + phys(ar, a_c));
            u32 br = (u32)(ks * 16) + b_radd;
#pragma unroll
            for (int np = 0; np < 4; np++) {
                u32 bH[4];
                u32 bc = (u32)(nhf * 8 + np * 2) + b_cadd;
                ldm4t(bH, sSH + phys(br, bc));
                mma16816(acc[2 * np],     aH, bH[0], bH[1]);
                mma16816(acc[2 * np + 1], aH, bH[2], bH[3]);
            }
        }
    }
    float* dst = g_gram_part[side][half];
    int r0 = m0 + (lane >> 2);
    int j0 = nhf * 64 + 2 * (lane & 3);
#pragma unroll
    for (int nt = 0; nt < 8; nt++) {
        int j = j0 + 8 * nt;
        *(float2*)&dst[r0 * DD + j]       = make_float2(acc[nt][0], acc[nt][1]);
        *(float2*)&dst[(r0 + 8) * DD + j] = make_float2(acc[nt][2], acc[nt][3]);
    }
}

// ---------------------------------------------------------------------------
// Kernel 3: reduce partials -> bf16 hi image
// ---------------------------------------------------------------------------
__global__ void reduce_split_kernel() {
    int idx = blockIdx.x * blockDim.x + threadIdx.x;
    int s = idx >> 14, e = idx & 16383;
    float v = g_gram_part[s][0][e] + g_gram_part[s][1][e];
    g_gimgH[s][e] = __float2bfloat16(v);
}

// ---------------------------------------------------------------------------
// Kernel 4: fused  V2 = Xh·Gh -> E build -> match GEMMs.  512 threads,
// 16 warps, warp = (m-tile mw, n-half nhf).  CTA = one 128-row tile.
// smem: XH XL (X, later E1=x^2 / E2=v^2), BH (G hi, later E0 hi),
//       BL (E0 lo only), WH (W2 hi).
// ---------------------------------------------------------------------------
#define FUSED_SMEM (5 * 32768)

__global__ void __launch_bounds__(512) fused_kernel(const float* __restrict__ feats,
                                                    float* __restrict__ out) {
    extern __shared__ __align__(16) unsigned char sm[];
    unsigned char* XH = sm;
    unsigned char* XL = sm + 32768;
    unsigned char* BH = sm + 65536;
    unsigned char* BL = sm + 98304;
    unsigned char* WH = sm + 131072;
    u32 sXH = s2u(sm), sXL = sXH + 32768;
    u32 sBH = sXH + 65536, sBL = sXH + 98304;
    u32 sWH = sXH + 131072;

    int blk = blockIdx.x, g = blk >> 4, tile = blk & 15;
    int t = threadIdx.x, wid = t >> 5, lane = t & 31;
    size_t lbase = (size_t)g * LL + (size_t)tile * 128;

    int mw = wid >> 1, nhf = wid & 1;
    int m0 = mw * 16;

    // ---- stage: X (split), G hi (partner), W2 (hi only)
    {
        const float4* xs = (const float4*)(feats + lbase * DD);
#pragma unroll
        for (int q = 0; q < 8; q++) {
            int idx = t + 512 * q;
            u32 r = (u32)(idx >> 5);
            u32 ln = (u32)(idx & 31);
            u32 off = phys(r, ln >> 1) + (ln & 1) * 8u;
            float4 v = xs[idx];
            u32 h0 = pk(v.x, v.y), h1 = pk(v.z, v.w);
            float2 f0 = upk(h0), f1 = upk(h1);
            u32 l0 = pk(v.x - f0.x, v.y - f0.y), l1 = pk(v.z - f1.x, v.w - f1.y);
            *(uint2*)(XH + off) = make_uint2(h0, h1);
            *(uint2*)(XL + off) = make_uint2(l0, l1);
        }
        const uint4* gh = (const uint4*)&g_gimgH[g ^ 1][0];
        const uint4* wh = (const uint4*)&g_w2H[0];
#pragma unroll
        for (int q = 0; q < 4; q++) {
            int idx = t + 512 * q;
            u32 r = (u32)(idx >> 4), ch = (u32)(idx & 15);
            u32 off = phys(r, ch);
            *(uint4*)(BH + off) = gh[idx];
            *(uint4*)(WH + off) = wh[idx];
        }
    }
    __syncthreads();

    u32 aA_r = (u32)m0 + (u32)(lane & 15);
    u32 aA_c = (u32)(lane >> 4);
    u32 bB_radd = (u32)((lane & 7) + (lane >> 4) * 8);
    u32 bB_cadd = (u32)((lane >> 3) & 1);

    // ---- GEMM1: V = Xh · Gh   (1-term); warp covers n in [nhf*64, +64)
    float vac[8][4];
#pragma unroll
    for (int i = 0; i < 8; i++) { vac[i][0] = vac[i][1] = vac[i][2] = vac[i][3] = 0.f; }
#pragma unroll
    for (int ks = 0; ks < 8; ks++) {
        u32 aH[4];
        u32 ac = (u32)(ks * 2) + aA_c;
        ldm4(aH, sXH + phys(aA_r, ac));
        u32 bc = (u32)(ks * 2) + bB_cadd;
#pragma unroll
        for (int np = 0; np < 4; np++) {
            u32 br = (u32)(nhf * 64 + np * 16) + bB_radd;
            u32 bH[4];
            ldm4(bH, sBH + phys(br, bc));
            mma16816(vac[2 * np],     aH, bH[0], bH[1]);
            mma16816(vac[2 * np + 1], aH, bH[2], bH[3]);
        }
    }
    __syncthreads();   // all GEMM1 smem reads complete before E overwrites

    // ---- E build: each thread owns exactly the elements it reads & writes
    // (rows of its m-tile, cols of its n-half).
    // E0 (x*v) split -> BH/BL ; E1 (x^2) -> XH ; E2 (v^2) -> XL.
    {
        u32 r = (u32)m0 + (u32)(lane >> 2);
        u32 sub = 4u * (u32)(lane & 3);
#pragma unroll
        for (int nt = 0; nt < 8; nt++) {
            u32 chunk = (u32)(nhf * 8 + nt);
            u32 offA = phys(r, chunk) + sub;          // (r+8)&7 == r&7 -> same xor
            u32 offB = phys(r + 8, chunk) + sub;
            {
                float2 xh = upk(*(u32*)(XH + offA));
                float2 xl = upk(*(u32*)(XL + offA));
                float x0 = xh.x + xl.x, x1 = xh.y + xl.y;
                float v0 = vac[nt][0], v1 = vac[nt][1];
                float e0 = x0 * v0, e1 = x1 * v1;
                u32 h = pk(e0, e1); float2 hf = upk(h);
                *(u32*)(BH + offA) = h;
                *(u32*)(BL + offA) = pk(e0 - hf.x, e1 - hf.y);
                *(u32*)(XH + offA) = pk(x0 * x0, x1 * x1);
                *(u32*)(XL + offA) = pk(v0 * v0, v1 * v1);
            }
            {
                float2 xh = upk(*(u32*)(XH + offB));
                float2 xl = upk(*(u32*)(XL + offB));
                float x0 = xh.x + xl.x, x1 = xh.y + xl.y;
                float v0 = vac[nt][2], v1 = vac[nt][3];
                float e0 = x0 * v0, e1 = x1 * v1;
                u32 h = pk(e0, e1); float2 hf = upk(h);
                *(u32*)(BH + offB) = h;
                *(u32*)(BL + offB) = pk(e0 - hf.x, e1 - hf.y);
                *(u32*)(XH + offB) = pk(x0 * x0, x1 * x1);
                *(u32*)(XL + offB) = pk(v0 * v0, v1 * v1);
            }
        }
    }
    __syncthreads();

    // ---- GEMM2 (+fused epilogue): warp covers p in [nhf*64, +64), two
    // passes of 32 perspectives to cap register pressure.
    float* outp = out + lbase * DD;
    int r0 = m0 + (lane >> 2);
#pragma unroll 1
    for (int pp = 0; pp < 2; pp++) {
        float aN[4][4], a1[4][4], a2[4][4];
#pragma unroll
        for (int i = 0; i < 4; i++) {
            aN[i][0] = aN[i][1] = aN[i][2] = aN[i][3] = 0.f;
            a1[i][0] = a1[i][1] = a1[i][2] = a1[i][3] = 0.f;
            a2[i][0] = a2[i][1] = a2[i][2] = a2[i][3] = 0.f;
        }
#pragma unroll
        for (int ks = 0; ks < 8; ks++) {
            u32 ac = (u32)(ks * 2) + aA_c;
            u32 aoff = phys(aA_r, ac);
            u32 e0h[4], e0l[4], e1f[4], e2f[4];
            ldm4(e0h, sBH + aoff);
            ldm4(e0l, sBL + aoff);
            ldm4(e1f, sXH + aoff);
            ldm4(e2f, sXL + aoff);
            u32 bc = (u32)(ks * 2) + bB_cadd;
#pragma unroll
            for (int np = 0; np < 2; np++) {
                u32 br = (u32)(nhf * 64 + pp * 32 + np * 16) + bB_radd;
                u32 wh[4];
                ldm4(wh, sWH + phys(br, bc));
                mma16816(aN[2 * np], e0h, wh[0], wh[1]);
                mma16816(aN[2 * np], e0l, wh[0], wh[1]);
                mma16816(a1[2 * np], e1f, wh[0], wh[1]);
                mma16816(a2[2 * np], e2f, wh[0], wh[1]);
                mma16816(aN[2 * np + 1], e0h, wh[2], wh[3]);
                mma16816(aN[2 * np + 1], e0l, wh[2], wh[3]);
                mma16816(a1[2 * np + 1], e1f, wh[2], wh[3]);
                mma16816(a2[2 * np + 1], e2f, wh[2], wh[3]);
            }
        }
#pragma unroll
        for (int nt = 0; nt < 4; nt++) {
            int p0 = nhf * 64 + pp * 32 + nt * 8 + 2 * (lane & 3);
            float d0 = fmaxf(sqrtf(a1[nt][0] * a2[nt][0]), 1e-8f);
            float d1 = fmaxf(sqrtf(a1[nt][1] * a2[nt][1]), 1e-8f);
            float d2 = fmaxf(sqrtf(a1[nt][2] * a2[nt][2]), 1e-8f);
            float d3 = fmaxf(sqrtf(a1[nt][3] * a2[nt][3]), 1e-8f);
            *(float2*)&outp[(size_t)r0 * DD + p0] =
                make_float2(__fdividef(aN[nt][0], d0), __fdividef(aN[nt][1], d1));
            *(float2*)&outp[(size_t)(r0 + 8) * DD + p0] =
                make_float2(__fdividef(aN[nt][2], d2), __fdividef(aN[nt][3], d3));
        }
    }
}

// ---------------------------------------------------------------------------
extern "C" void kernel_launch(void* const* d_in, const int* in_sizes, int n_in,
                              void* d_out, int out_size) {
    const float* feats = (const float*)d_in[0];
    const float* mp_w  = (const float*)d_in[1];
    float* out = (float*)d_out;

    cudaFuncSetAttribute(fused_kernel, cudaFuncAttributeMaxDynamicSharedMemorySize, FUSED_SMEM);

    w2img_kernel<<<64, 256>>>(mp_w);
    gram_kernel<<<NG * 2, 512, 32768>>>(feats);
    reduce_split_kernel<<<(NG * DD * DD) / 256, 256>>>();
    fused_kernel<<<NG * (LL / 128), 512, FUSED_SMEM>>>(feats, out);
}

// round 14
// speedup vs baseline: 1.6204x; 1.1133x over previous
#include <cuda_runtime.h>
#include <cuda_bf16.h>
#include <cstdint>

// Problem constants: 64 graph-sides x 2048 rows x 128 dim.
#define NG 64
#define LL 2048
#define DD 128

typedef unsigned int u32;

__device__ __forceinline__ u32 s2u(const void* p) {
    u32 a; asm("{ .reg .u64 t; cvta.to.shared.u64 t, %1; cvt.u32.u64 %0, t; }" : "=r"(a) : "l"(p)); return a;
}
// 128x128 bf16 tile, 256B rows, 16B-chunk XOR swizzle (conflict-free ldmatrix).
__device__ __forceinline__ u32 phys(u32 r, u32 c) { return r * 256u + (((c ^ (r & 7u)) << 4)); }

__device__ __forceinline__ void ldm4(u32* r, u32 a) {
    asm volatile("ldmatrix.sync.aligned.m8n8.x4.shared.b16 {%0,%1,%2,%3}, [%4];"
                 : "=r"(r[0]), "=r"(r[1]), "=r"(r[2]), "=r"(r[3]) : "r"(a));
}
__device__ __forceinline__ void ldm4t(u32* r, u32 a) {
    asm volatile("ldmatrix.sync.aligned.m8n8.x4.trans.shared.b16 {%0,%1,%2,%3}, [%4];"
                 : "=r"(r[0]), "=r"(r[1]), "=r"(r[2]), "=r"(r[3]) : "r"(a));
}
__device__ __forceinline__ void mma16816(float* c, const u32* a, u32 b0, u32 b1) {
    asm volatile("mma.sync.aligned.m16n8k16.row.col.f32.bf16.bf16.f32 "
        "{%0,%1,%2,%3}, {%4,%5,%6,%7}, {%8,%9}, {%0,%1,%2,%3};"
        : "+f"(c[0]), "+f"(c[1]), "+f"(c[2]), "+f"(c[3])
        : "r"(a[0]), "r"(a[1]), "r"(a[2]), "r"(a[3]), "r"(b0), "r"(b1));
}

__device__ __forceinline__ u32 pk(float a, float b) {
    __nv_bfloat162 t = __floats2bfloat162_rn(a, b); return *(u32*)&t;
}
__device__ __forceinline__ float2 upk(u32 v) {
    return __bfloat1622float2(*(__nv_bfloat162*)&v);
}

// Scratch (plain row-major in gmem; swizzle applied at smem staging)
__device__ float g_gram_part[NG][2][DD * DD];
__device__ __align__(16) __nv_bfloat16 g_gimgH[NG][DD * DD];
__device__ __align__(16) __nv_bfloat16 g_w2H[DD * DD];

// ---------------------------------------------------------------------------
// Kernel 1: W2 = mp_w^2, hi image only (consistent-weight perturbation)
// ---------------------------------------------------------------------------
__global__ void w2img_kernel(const float* __restrict__ mp_w) {
    int idx = blockIdx.x * blockDim.x + threadIdx.x;
    if (idx < DD * DD) {
        float w = mp_w[idx];
        g_w2H[idx] = __float2bfloat16(w * w);
    }
}

// ---------------------------------------------------------------------------
// Kernel 2: Gram partials.  CTA = (side, K-half), 512 threads / 16 warps.
// warp = (m-tile, n-half).  C = Xh^T Xh  (1-term).
// ---------------------------------------------------------------------------
__global__ void __launch_bounds__(512) gram_kernel(const float* __restrict__ feats) {
    extern __shared__ __align__(16) unsigned char sm[];
    unsigned char* SH = sm;
    u32 sSH = s2u(sm);

    int side = blockIdx.x >> 1, half = blockIdx.x & 1;
    int t = threadIdx.x, wid = t >> 5, lane = t & 31;
    const float4* X = (const float4*)(feats + ((size_t)side * LL + (size_t)half * 1024) * DD);

    int mw = wid >> 1, nhf = wid & 1;
    int m0 = mw * 16;

    float acc[8][4];
#pragma unroll
    for (int i = 0; i < 8; i++) { acc[i][0] = acc[i][1] = acc[i][2] = acc[i][3] = 0.f; }

    float4 pv[8];
#pragma unroll
    for (int q = 0; q < 8; q++) pv[q] = X[t + 512 * q];

    u32 a_radd = (u32)((lane & 7) + ((lane >> 4) & 1) * 8);
    u32 a_c    = (u32)(mw * 2) + (u32)((lane >> 3) & 1);
    u32 b_radd = (u32)((lane & 7) + ((lane >> 3) & 1) * 8);
    u32 b_cadd = (u32)(lane >> 4);

    for (int c = 0; c < 8; c++) {
        __syncthreads();     // previous compute done with smem
#pragma unroll
        for (int q = 0; q < 8; q++) {
            u32 r = (u32)(wid + 16 * q);
            u32 off = phys(r, (u32)(lane >> 1)) + (u32)(lane & 1) * 8u;
            float4 v = pv[q];
            *(uint2*)(SH + off) = make_uint2(pk(v.x, v.y), pk(v.z, v.w));
        }
        __syncthreads();
        if (c < 7) {   // prefetch next chunk; latency overlaps compute
            const float4* Xn = X + (size_t)(c + 1) * 4096;
#pragma unroll
            for (int q = 0; q < 8; q++) pv[q] = Xn[t + 512 * q];
        }
#pragma unroll
        for (int ks = 0; ks < 8; ks++) {
            u32 aH[4];
            u32 ar = (u32)(ks * 16) + a_radd;
            ldm4t(aH, sSH + phys(ar, a_c));
            u32 br = (u32)(ks * 16) + b_radd;
#pragma unroll
            for (int np = 0; np < 4; np++) {
                u32 bH[4];
                u32 bc = (u32)(nhf * 8 + np * 2) + b_cadd;
                ldm4t(bH, sSH + phys(br, bc));
                mma16816(acc[2 * np],     aH, bH[0], bH[1]);
                mma16816(acc[2 * np + 1], aH, bH[2], bH[3]);
            }
        }
    }
    float* dst = g_gram_part[side][half];
    int r0 = m0 + (lane >> 2);
    int j0 = nhf * 64 + 2 * (lane & 3);
#pragma unroll
    for (int nt = 0; nt < 8; nt++) {
        int j = j0 + 8 * nt;
        *(float2*)&dst[r0 * DD + j]       = make_float2(acc[nt][0], acc[nt][1]);
        *(float2*)&dst[(r0 + 8) * DD + j] = make_float2(acc[nt][2], acc[nt][3]);
    }
}

// ---------------------------------------------------------------------------
// Kernel 3: reduce partials -> bf16 hi image
// ---------------------------------------------------------------------------
__global__ void reduce_split_kernel() {
    int idx = blockIdx.x * blockDim.x + threadIdx.x;
    int s = idx >> 14, e = idx & 16383;
    float v = g_gram_part[s][0][e] + g_gram_part[s][1][e];
    g_gimgH[s][e] = __float2bfloat16(v);
}

// ---------------------------------------------------------------------------
// Kernel 4: fused  V2 = Xh·Gh -> E build -> match GEMMs.  512 threads,
// 16 warps, warp = (m-tile mw, n-half nhf).  CTA = one 128-row tile.
// smem: XH XL (X, later E1=x^2 / E2=v^2), BH (G hi, later E0 hi), WH (W2 hi).
// 128 KB total.
// ---------------------------------------------------------------------------
#define FUSED_SMEM (4 * 32768)

__global__ void __launch_bounds__(512) fused_kernel(const float* __restrict__ feats,
                                                    float* __restrict__ out) {
    extern __shared__ __align__(16) unsigned char sm[];
    unsigned char* XH = sm;
    unsigned char* XL = sm + 32768;
    unsigned char* BH = sm + 65536;
    unsigned char* WH = sm + 98304;
    u32 sXH = s2u(sm), sXL = sXH + 32768;
    u32 sBH = sXH + 65536;
    u32 sWH = sXH + 98304;

    int blk = blockIdx.x, g = blk >> 4, tile = blk & 15;
    int t = threadIdx.x, wid = t >> 5, lane = t & 31;
    size_t lbase = (size_t)g * LL + (size_t)tile * 128;

    int mw = wid >> 1, nhf = wid & 1;
    int m0 = mw * 16;

    // ---- stage: X (split), G hi (partner), W2 (hi only)
    {
        const float4* xs = (const float4*)(feats + lbase * DD);
#pragma unroll
        for (int q = 0; q < 8; q++) {
            int idx = t + 512 * q;
            u32 r = (u32)(idx >> 5);
            u32 ln = (u32)(idx & 31);
            u32 off = phys(r, ln >> 1) + (ln & 1) * 8u;
            float4 v = xs[idx];
            u32 h0 = pk(v.x, v.y), h1 = pk(v.z, v.w);
            float2 f0 = upk(h0), f1 = upk(h1);
            u32 l0 = pk(v.x - f0.x, v.y - f0.y), l1 = pk(v.z - f1.x, v.w - f1.y);
            *(uint2*)(XH + off) = make_uint2(h0, h1);
            *(uint2*)(XL + off) = make_uint2(l0, l1);
        }
        const uint4* gh = (const uint4*)&g_gimgH[g ^ 1][0];
        const uint4* wh = (const uint4*)&g_w2H[0];
#pragma unroll
        for (int q = 0; q < 4; q++) {
            int idx = t + 512 * q;
            u32 r = (u32)(idx >> 4), ch = (u32)(idx & 15);
            u32 off = phys(r, ch);
            *(uint4*)(BH + off) = gh[idx];
            *(uint4*)(WH + off) = wh[idx];
        }
    }
    __syncthreads();

    u32 aA_r = (u32)m0 + (u32)(lane & 15);
    u32 aA_c = (u32)(lane >> 4);
    u32 bB_radd = (u32)((lane & 7) + (lane >> 4) * 8);
    u32 bB_cadd = (u32)((lane >> 3) & 1);

    // ---- GEMM1: V = Xh · Gh   (1-term); warp covers n in [nhf*64, +64)
    float vac[8][4];
#pragma unroll
    for (int i = 0; i < 8; i++) { vac[i][0] = vac[i][1] = vac[i][2] = vac[i][3] = 0.f; }
#pragma unroll
    for (int ks = 0; ks < 8; ks++) {
        u32 aH[4];
        u32 ac = (u32)(ks * 2) + aA_c;
        ldm4(aH, sXH + phys(aA_r, ac));
        u32 bc = (u32)(ks * 2) + bB_cadd;
#pragma unroll
        for (int np = 0; np < 4; np++) {
            u32 br = (u32)(nhf * 64 + np * 16) + bB_radd;
            u32 bH[4];
            ldm4(bH, sBH + phys(br, bc));
            mma16816(vac[2 * np],     aH, bH[0], bH[1]);
            mma16816(vac[2 * np + 1], aH, bH[2], bH[3]);
        }
    }
    __syncthreads();   // all GEMM1 smem reads complete before E overwrites

    // ---- E build: each thread owns exactly the elements it reads & writes
    // (rows of its m-tile, cols of its n-half).
    // E0 (x*v) hi-only -> BH ; E1 (x^2) -> XH ; E2 (v^2) -> XL.
    {
        u32 r = (u32)m0 + (u32)(lane >> 2);
        u32 sub = 4u * (u32)(lane & 3);
#pragma unroll
        for (int nt = 0; nt < 8; nt++) {
            u32 chunk = (u32)(nhf * 8 + nt);
            u32 offA = phys(r, chunk) + sub;          // (r+8)&7 == r&7 -> same xor
            u32 offB = phys(r + 8, chunk) + sub;
            {
                float2 xh = upk(*(u32*)(XH + offA));
                float2 xl = upk(*(u32*)(XL + offA));
                float x0 = xh.x + xl.x, x1 = xh.y + xl.y;
                float v0 = vac[nt][0], v1 = vac[nt][1];
                *(u32*)(BH + offA) = pk(x0 * v0, x1 * v1);
                *(u32*)(XH + offA) = pk(x0 * x0, x1 * x1);
                *(u32*)(XL + offA) = pk(v0 * v0, v1 * v1);
            }
            {
                float2 xh = upk(*(u32*)(XH + offB));
                float2 xl = upk(*(u32*)(XL + offB));
                float x0 = xh.x + xl.x, x1 = xh.y + xl.y;
                float v0 = vac[nt][2], v1 = vac[nt][3];
                *(u32*)(BH + offB) = pk(x0 * v0, x1 * v1);
                *(u32*)(XH + offB) = pk(x0 * x0, x1 * x1);
                *(u32*)(XL + offB) = pk(v0 * v0, v1 * v1);
            }
        }
    }
    __syncthreads();

    // ---- GEMM2 (+fused epilogue): warp covers p in [nhf*64, +64), two
    // passes of 32 perspectives to cap register pressure.
    float* outp = out + lbase * DD;
    int r0 = m0 + (lane >> 2);
#pragma unroll 1
    for (int pp = 0; pp < 2; pp++) {
        float aN[4][4], a1[4][4], a2[4][4];
#pragma unroll
        for (int i = 0; i < 4; i++) {
            aN[i][0] = aN[i][1] = aN[i][2] = aN[i][3] = 0.f;
            a1[i][0] = a1[i][1] = a1[i][2] = a1[i][3] = 0.f;
            a2[i][0] = a2[i][1] = a2[i][2] = a2[i][3] = 0.f;
        }
#pragma unroll
        for (int ks = 0; ks < 8; ks++) {
            u32 ac = (u32)(ks * 2) + aA_c;
            u32 aoff = phys(aA_r, ac);
            u32 e0f[4], e1f[4], e2f[4];
            ldm4(e0f, sBH + aoff);
            ldm4(e1f, sXH + aoff);
            ldm4(e2f, sXL + aoff);
            u32 bc = (u32)(ks * 2) + bB_cadd;
#pragma unroll
            for (int np = 0; np < 2; np++) {
                u32 br = (u32)(nhf * 64 + pp * 32 + np * 16) + bB_radd;
                u32 wh[4];
                ldm4(wh, sWH + phys(br, bc));
                mma16816(aN[2 * np], e0f, wh[0], wh[1]);
                mma16816(a1[2 * np], e1f, wh[0], wh[1]);
                mma16816(a2[2 * np], e2f, wh[0], wh[1]);
                mma16816(aN[2 * np + 1], e0f, wh[2], wh[3]);
                mma16816(a1[2 * np + 1], e1f, wh[2], wh[3]);
                mma16816(a2[2 * np + 1], e2f, wh[2], wh[3]);
            }
        }
#pragma unroll
        for (int nt = 0; nt < 4; nt++) {
            int p0 = nhf * 64 + pp * 32 + nt * 8 + 2 * (lane & 3);
            float d0 = fmaxf(sqrtf(a1[nt][0] * a2[nt][0]), 1e-8f);
            float d1 = fmaxf(sqrtf(a1[nt][1] * a2[nt][1]), 1e-8f);
            float d2 = fmaxf(sqrtf(a1[nt][2] * a2[nt][2]), 1e-8f);
            float d3 = fmaxf(sqrtf(a1[nt][3] * a2[nt][3]), 1e-8f);
            *(float2*)&outp[(size_t)r0 * DD + p0] =
                make_float2(__fdividef(aN[nt][0], d0), __fdividef(aN[nt][1], d1));
            *(float2*)&outp[(size_t)(r0 + 8) * DD + p0] =
                make_float2(__fdividef(aN[nt][2], d2), __fdividef(aN[nt][3], d3));
        }
    }
}

// ---------------------------------------------------------------------------
extern "C" void kernel_launch(void* const* d_in, const int* in_sizes, int n_in,
                              void* d_out, int out_size) {
    const float* feats = (const float*)d_in[0];
    const float* mp_w  = (const float*)d_in[1];
    float* out = (float*)d_out;

    cudaFuncSetAttribute(fused_kernel, cudaFuncAttributeMaxDynamicSharedMemorySize, FUSED_SMEM);

    w2img_kernel<<<64, 256>>>(mp_w);
    gram_kernel<<<NG * 2, 512, 32768>>>(feats);
    reduce_split_kernel<<<(NG * DD * DD) / 256, 256>>>();
    fused_kernel<<<NG * (LL / 128), 512, FUSED_SMEM>>>(feats, out);
}

// round 16
// speedup vs baseline: 1.8425x; 1.1371x over previous
#include <cuda_runtime.h>
#include <cuda_bf16.h>
#include <cstdint>

// Problem constants: 64 graph-sides x 2048 rows x 128 dim.
#define NG 64
#define LL 2048
#define DD 128

typedef unsigned int u32;

__device__ __forceinline__ u32 s2u(const void* p) {
    u32 a; asm("{ .reg .u64 t; cvta.to.shared.u64 t, %1; cvt.u32.u64 %0, t; }" : "=r"(a) : "l"(p)); return a;
}
// 128x128 bf16 tile, 256B rows, 16B-chunk XOR swizzle (conflict-free ldmatrix).
__device__ __forceinline__ u32 phys(u32 r, u32 c) { return r * 256u + (((c ^ (r & 7u)) << 4)); }

__device__ __forceinline__ void ldm4(u32* r, u32 a) {
    asm volatile("ldmatrix.sync.aligned.m8n8.x4.shared.b16 {%0,%1,%2,%3}, [%4];"
                 : "=r"(r[0]), "=r"(r[1]), "=r"(r[2]), "=r"(r[3]) : "r"(a));
}
__device__ __forceinline__ void ldm4t(u32* r, u32 a) {
    asm volatile("ldmatrix.sync.aligned.m8n8.x4.trans.shared.b16 {%0,%1,%2,%3}, [%4];"
                 : "=r"(r[0]), "=r"(r[1]), "=r"(r[2]), "=r"(r[3]) : "r"(a));
}
__device__ __forceinline__ void mma16816(float* c, const u32* a, u32 b0, u32 b1) {
    asm volatile("mma.sync.aligned.m16n8k16.row.col.f32.bf16.bf16.f32 "
        "{%0,%1,%2,%3}, {%4,%5,%6,%7}, {%8,%9}, {%0,%1,%2,%3};"
        : "+f"(c[0]), "+f"(c[1]), "+f"(c[2]), "+f"(c[3])
        : "r"(a[0]), "r"(a[1]), "r"(a[2]), "r"(a[3]), "r"(b0), "r"(b1));
}

__device__ __forceinline__ u32 pk(float a, float b) {
    __nv_bfloat162 t = __floats2bfloat162_rn(a, b); return *(u32*)&t;
}
__device__ __forceinline__ float2 upk(u32 v) {
    return __bfloat1622float2(*(__nv_bfloat162*)&v);
}
__device__ __forceinline__ u32 hmul2(u32 a, u32 b) {
    u32 d; asm("mul.bf16x2 %0, %1, %2;" : "=r"(d) : "r"(a), "r"(b)); return d;
}

// Scratch (plain row-major in gmem; swizzle applied at smem staging)
__device__ float g_gram_part[NG][2][DD * DD];
__device__ __align__(16) __nv_bfloat16 g_gimgH[NG][DD * DD];
__device__ __align__(16) __nv_bfloat16 g_w2H[DD * DD];

// ---------------------------------------------------------------------------
// Kernel 1: W2 = mp_w^2, hi image only (consistent-weight perturbation)
// ---------------------------------------------------------------------------
__global__ void w2img_kernel(const float* __restrict__ mp_w) {
    int idx = blockIdx.x * blockDim.x + threadIdx.x;
    if (idx < DD * DD) {
        float w = mp_w[idx];
        g_w2H[idx] = __float2bfloat16(w * w);
    }
}

// ---------------------------------------------------------------------------
// Kernel 2: Gram partials.  CTA = (side, K-half), 512 threads / 16 warps.
// warp = (m-tile, n-half).  C = Xh^T Xh  (1-term).
// ---------------------------------------------------------------------------
__global__ void __launch_bounds__(512) gram_kernel(const float* __restrict__ feats) {
    extern __shared__ __align__(16) unsigned char sm[];
    unsigned char* SH = sm;
    u32 sSH = s2u(sm);

    int side = blockIdx.x >> 1, half = blockIdx.x & 1;
    int t = threadIdx.x, wid = t >> 5, lane = t & 31;
    const float4* X = (const float4*)(feats + ((size_t)side * LL + (size_t)half * 1024) * DD);

    int mw = wid >> 1, nhf = wid & 1;
    int m0 = mw * 16;

    float acc[8][4];
#pragma unroll
    for (int i = 0; i < 8; i++) { acc[i][0] = acc[i][1] = acc[i][2] = acc[i][3] = 0.f; }

    float4 pv[8];
#pragma unroll
    for (int q = 0; q < 8; q++) pv[q] = X[t + 512 * q];

    u32 a_radd = (u32)((lane & 7) + ((lane >> 4) & 1) * 8);
    u32 a_c    = (u32)(mw * 2) + (u32)((lane >> 3) & 1);
    u32 b_radd = (u32)((lane & 7) + ((lane >> 3) & 1) * 8);
    u32 b_cadd = (u32)(lane >> 4);

    for (int c = 0; c < 8; c++) {
        __syncthreads();     // previous compute done with smem
#pragma unroll
        for (int q = 0; q < 8; q++) {
            u32 r = (u32)(wid + 16 * q);
            u32 off = phys(r, (u32)(lane >> 1)) + (u32)(lane & 1) * 8u;
            float4 v = pv[q];
            *(uint2*)(SH + off) = make_uint2(pk(v.x, v.y), pk(v.z, v.w));
        }
        __syncthreads();
        if (c < 7) {   // prefetch next chunk; latency overlaps compute
            const float4* Xn = X + (size_t)(c + 1) * 4096;
#pragma unroll
            for (int q = 0; q < 8; q++) pv[q] = Xn[t + 512 * q];
        }
#pragma unroll
        for (int ks = 0; ks < 8; ks++) {
            u32 aH[4];
            u32 ar = (u32)(ks * 16) + a_radd;
            ldm4t(aH, sSH + phys(ar, a_c));
            u32 br = (u32)(ks * 16) + b_radd;
#pragma unroll
            for (int np = 0; np < 4; np++) {
                u32 bH[4];
                u32 bc = (u32)(nhf * 8 + np * 2) + b_cadd;
                ldm4t(bH, sSH + phys(br, bc));
                mma16816(acc[2 * np],     aH, bH[0], bH[1]);
                mma16816(acc[2 * np + 1], aH, bH[2], bH[3]);
            }
        }
    }
    float* dst = g_gram_part[side][half];
    int r0 = m0 + (lane >> 2);
    int j0 = nhf * 64 + 2 * (lane & 3);
#pragma unroll
    for (int nt = 0; nt < 8; nt++) {
        int j = j0 + 8 * nt;
        *(float2*)&dst[r0 * DD + j]       = make_float2(acc[nt][0], acc[nt][1]);
        *(float2*)&dst[(r0 + 8) * DD + j] = make_float2(acc[nt][2], acc[nt][3]);
    }
}

// ---------------------------------------------------------------------------
// Kernel 3: reduce partials -> bf16 hi image
// ---------------------------------------------------------------------------
__global__ void reduce_split_kernel() {
    int idx = blockIdx.x * blockDim.x + threadIdx.x;
    int s = idx >> 14, e = idx & 16383;
    float v = g_gram_part[s][0][e] + g_gram_part[s][1][e];
    g_gimgH[s][e] = __float2bfloat16(v);
}

// ---------------------------------------------------------------------------
// Kernel 4: fused  V = Xh·Gh -> in-register E-frags -> match GEMMs.
// 256 threads / 8 warps, warp = one 16-row m-tile covering FULL n/k/p range.
// GEMM1's C-fragment layout == GEMM2's A-fragment layout, so E0/E1/E2
// fragments are built with mul.bf16x2 from packed V (regs) and X (4 scalar
// conflict-free LDS per k-chunk) — E never touches smem.  One __syncthreads
// total; smem = XH + GH + WH = 96 KB -> 2 CTAs/SM.
// ---------------------------------------------------------------------------
#define FUSED_SMEM (3 * 32768)

__global__ void __launch_bounds__(256, 2) fused_kernel(const float* __restrict__ feats,
                                                       float* __restrict__ out) {
    extern __shared__ __align__(16) unsigned char sm[];
    unsigned char* XH = sm;
    unsigned char* BH = sm + 32768;
    unsigned char* WH = sm + 65536;
    u32 sXH = s2u(sm);
    u32 sBH = sXH + 32768;
    u32 sWH = sXH + 65536;

    int blk = blockIdx.x, g = blk >> 4, tile = blk & 15;
    int t = threadIdx.x, wid = t >> 5, lane = t & 31;
    size_t lbase = (size_t)g * LL + (size_t)tile * 128;

    int m0 = wid * 16;

    // ---- stage: X (hi only), G hi (partner), W2 (hi)
    {
        const float4* xs = (const float4*)(feats + lbase * DD);
#pragma unroll
        for (int q = 0; q < 16; q++) {
            int idx = t + 256 * q;
            u32 r = (u32)(idx >> 5);
            u32 ln = (u32)(idx & 31);
            u32 off = phys(r, ln >> 1) + (ln & 1) * 8u;
            float4 v = xs[idx];
            *(uint2*)(XH + off) = make_uint2(pk(v.x, v.y), pk(v.z, v.w));
        }
        const uint4* gh = (const uint4*)&g_gimgH[g ^ 1][0];
        const uint4* wh = (const uint4*)&g_w2H[0];
#pragma unroll
        for (int q = 0; q < 8; q++) {
            int idx = t + 256 * q;
            u32 r = (u32)(idx >> 4), ch = (u32)(idx & 15);
            u32 off = phys(r, ch);
            *(uint4*)(BH + off) = gh[idx];
            *(uint4*)(WH + off) = wh[idx];
        }
    }
    __syncthreads();   // the ONLY block-wide sync

    u32 aA_r = (u32)m0 + (u32)(lane & 15);
    u32 aA_c = (u32)(lane >> 4);
    u32 bB_radd = (u32)((lane & 7) + (lane >> 4) * 8);
    u32 bB_cadd = (u32)((lane >> 3) & 1);

    // ---- GEMM1: V = Xh · Gh, full n = 128 (16 n-tiles per warp)
    float vac[16][4];
#pragma unroll
    for (int i = 0; i < 16; i++) { vac[i][0] = vac[i][1] = vac[i][2] = vac[i][3] = 0.f; }
#pragma unroll
    for (int ks = 0; ks < 8; ks++) {
        u32 aH[4];
        u32 ac = (u32)(ks * 2) + aA_c;
        ldm4(aH, sXH + phys(aA_r, ac));
        u32 bc = (u32)(ks * 2) + bB_cadd;
#pragma unroll
        for (int np = 0; np < 8; np++) {
            u32 br = (u32)(np * 16) + bB_radd;
            u32 bH[4];
            ldm4(bH, sBH + phys(br, bc));
            mma16816(vac[2 * np],     aH, bH[0], bH[1]);
            mma16816(vac[2 * np + 1], aH, bH[2], bH[3]);
        }
    }

    // ---- pack V to bf16 pairs in C-fragment layout (== A-frag layout for GEMM2)
    u32 vpk[32];
#pragma unroll
    for (int nt = 0; nt < 16; nt++) {
        vpk[2 * nt]     = pk(vac[nt][0], vac[nt][1]);
        vpk[2 * nt + 1] = pk(vac[nt][2], vac[nt][3]);
    }

    // ---- GEMM2 (+fused epilogue): 4 passes of 32 perspectives.
    // A-frags per k-chunk ks built in regs: v from vpk[4ks..4ks+3],
    // x from 4 conflict-free LDS.32, E = mul.bf16x2.
    float* outp = out + lbase * DD;
    u32 r0 = (u32)m0 + (u32)(lane >> 2);
    u32 sub = 4u * (u32)(lane & 3);
#pragma unroll 1
    for (int pp = 0; pp < 4; pp++) {
        float aN[4][4], a1[4][4], a2[4][4];
#pragma unroll
        for (int i = 0; i < 4; i++) {
            aN[i][0] = aN[i][1] = aN[i][2] = aN[i][3] = 0.f;
            a1[i][0] = a1[i][1] = a1[i][2] = a1[i][3] = 0.f;
            a2[i][0] = a2[i][1] = a2[i][2] = a2[i][3] = 0.f;
        }
#pragma unroll
        for (int ks = 0; ks < 8; ks++) {
            u32 xp[4];
            xp[0] = *(const u32*)(XH + phys(r0,     (u32)(2 * ks))     + sub);
            xp[1] = *(const u32*)(XH + phys(r0 + 8, (u32)(2 * ks))     + sub);
            xp[2] = *(const u32*)(XH + phys(r0,     (u32)(2 * ks + 1)) + sub);
            xp[3] = *(const u32*)(XH + phys(r0 + 8, (u32)(2 * ks + 1)) + sub);
            u32 e0[4], e1[4], e2[4];
#pragma unroll
            for (int j = 0; j < 4; j++) {
                u32 vp = vpk[4 * ks + j];
                e0[j] = hmul2(xp[j], vp);
                e1[j] = hmul2(xp[j], xp[j]);
                e2[j] = hmul2(vp, vp);
            }
            u32 bc = (u32)(ks * 2) + bB_cadd;
#pragma unroll
            for (int np = 0; np < 2; np++) {
                u32 br = (u32)(pp * 32 + np * 16) + bB_radd;
                u32 wh[4];
                ldm4(wh, sWH + phys(br, bc));
                mma16816(aN[2 * np], e0, wh[0], wh[1]);
                mma16816(a1[2 * np], e1, wh[0], wh[1]);
                mma16816(a2[2 * np], e2, wh[0], wh[1]);
                mma16816(aN[2 * np + 1], e0, wh[2], wh[3]);
                mma16816(a1[2 * np + 1], e1, wh[2], wh[3]);
                mma16816(a2[2 * np + 1], e2, wh[2], wh[3]);
            }
        }
#pragma unroll
        for (int nt = 0; nt < 4; nt++) {
            int p0 = pp * 32 + nt * 8 + 2 * (lane & 3);
            float d0 = fmaxf(sqrtf(a1[nt][0] * a2[nt][0]), 1e-8f);
            float d1 = fmaxf(sqrtf(a1[nt][1] * a2[nt][1]), 1e-8f);
            float d2 = fmaxf(sqrtf(a1[nt][2] * a2[nt][2]), 1e-8f);
            float d3 = fmaxf(sqrtf(a1[nt][3] * a2[nt][3]), 1e-8f);
            *(float2*)&outp[(size_t)r0 * DD + p0] =
                make_float2(__fdividef(aN[nt][0], d0), __fdividef(aN[nt][1], d1));
            *(float2*)&outp[(size_t)(r0 + 8) * DD + p0] =
                make_float2(__fdividef(aN[nt][2], d2), __fdividef(aN[nt][3], d3));
        }
    }
}

// ---------------------------------------------------------------------------
extern "C" void kernel_launch(void* const* d_in, const int* in_sizes, int n_in,
                              void* d_out, int out_size) {
    const float* feats = (const float*)d_in[0];
    const float* mp_w  = (const float*)d_in[1];
    float* out = (float*)d_out;

    cudaFuncSetAttribute(fused_kernel, cudaFuncAttributeMaxDynamicSharedMemorySize, FUSED_SMEM);

    w2img_kernel<<<64, 256>>>(mp_w);
    gram_kernel<<<NG * 2, 512, 32768>>>(feats);
    reduce_split_kernel<<<(NG * DD * DD) / 256, 256>>>();
    fused_kernel<<<NG * (LL / 128), 256, FUSED_SMEM>>>(feats, out);
}

// round 17
// speedup vs baseline: 1.9431x; 1.0546x over previous
#include <cuda_runtime.h>
#include <cuda_bf16.h>
#include <cstdint>

// Problem constants: 64 graph-sides x 2048 rows x 128 dim.
#define NG 64
#define LL 2048
#define DD 128

typedef unsigned int u32;

__device__ __forceinline__ u32 s2u(const void* p) {
    u32 a; asm("{ .reg .u64 t; cvta.to.shared.u64 t, %1; cvt.u32.u64 %0, t; }" : "=r"(a) : "l"(p)); return a;
}
// 128x128 bf16 tile, 256B rows, 16B-chunk XOR swizzle (conflict-free ldmatrix).
__device__ __forceinline__ u32 phys(u32 r, u32 c) { return r * 256u + (((c ^ (r & 7u)) << 4)); }

__device__ __forceinline__ void ldm4(u32* r, u32 a) {
    asm volatile("ldmatrix.sync.aligned.m8n8.x4.shared.b16 {%0,%1,%2,%3}, [%4];"
                 : "=r"(r[0]), "=r"(r[1]), "=r"(r[2]), "=r"(r[3]) : "r"(a));
}
__device__ __forceinline__ void ldm4t(u32* r, u32 a) {
    asm volatile("ldmatrix.sync.aligned.m8n8.x4.trans.shared.b16 {%0,%1,%2,%3}, [%4];"
                 : "=r"(r[0]), "=r"(r[1]), "=r"(r[2]), "=r"(r[3]) : "r"(a));
}
__device__ __forceinline__ void mma16816(float* c, const u32* a, u32 b0, u32 b1) {
    asm volatile("mma.sync.aligned.m16n8k16.row.col.f32.bf16.bf16.f32 "
        "{%0,%1,%2,%3}, {%4,%5,%6,%7}, {%8,%9}, {%0,%1,%2,%3};"
        : "+f"(c[0]), "+f"(c[1]), "+f"(c[2]), "+f"(c[3])
        : "r"(a[0]), "r"(a[1]), "r"(a[2]), "r"(a[3]), "r"(b0), "r"(b1));
}

__device__ __forceinline__ u32 pk(float a, float b) {
    __nv_bfloat162 t = __floats2bfloat162_rn(a, b); return *(u32*)&t;
}
__device__ __forceinline__ float2 upk(u32 v) {
    return __bfloat1622float2(*(__nv_bfloat162*)&v);
}
__device__ __forceinline__ u32 hmul2(u32 a, u32 b) {
    u32 d; asm("mul.bf16x2 %0, %1, %2;" : "=r"(d) : "r"(a), "r"(b)); return d;
}

// Scratch (plain row-major in gmem; swizzle applied at smem staging)
__device__ float g_gram_part[NG][2][DD * DD];
__device__ __align__(16) __nv_bfloat16 g_gimgH[NG][DD * DD];
__device__ __align__(16) __nv_bfloat16 g_w2H[DD * DD];

// ---------------------------------------------------------------------------
// Kernel 1: Gram partials.  CTA = (side, K-half), 512 threads / 16 warps.
// warp = (m-tile, n-half).  C = Xh^T Xh  (1-term).
// ---------------------------------------------------------------------------
__global__ void __launch_bounds__(512) gram_kernel(const float* __restrict__ feats) {
    extern __shared__ __align__(16) unsigned char sm[];
    unsigned char* SH = sm;
    u32 sSH = s2u(sm);

    int side = blockIdx.x >> 1, half = blockIdx.x & 1;
    int t = threadIdx.x, wid = t >> 5, lane = t & 31;
    const float4* X = (const float4*)(feats + ((size_t)side * LL + (size_t)half * 1024) * DD);

    int mw = wid >> 1, nhf = wid & 1;
    int m0 = mw * 16;

    float acc[8][4];
#pragma unroll
    for (int i = 0; i < 8; i++) { acc[i][0] = acc[i][1] = acc[i][2] = acc[i][3] = 0.f; }

    float4 pv[8];
#pragma unroll
    for (int q = 0; q < 8; q++) pv[q] = X[t + 512 * q];

    u32 a_radd = (u32)((lane & 7) + ((lane >> 4) & 1) * 8);
    u32 a_c    = (u32)(mw * 2) + (u32)((lane >> 3) & 1);
    u32 b_radd = (u32)((lane & 7) + ((lane >> 3) & 1) * 8);
    u32 b_cadd = (u32)(lane >> 4);

    for (int c = 0; c < 8; c++) {
        __syncthreads();     // previous compute done with smem
#pragma unroll
        for (int q = 0; q < 8; q++) {
            u32 r = (u32)(wid + 16 * q);
            u32 off = phys(r, (u32)(lane >> 1)) + (u32)(lane & 1) * 8u;
            float4 v = pv[q];
            *(uint2*)(SH + off) = make_uint2(pk(v.x, v.y), pk(v.z, v.w));
        }
        __syncthreads();
        if (c < 7) {   // prefetch next chunk; latency overlaps compute
            const float4* Xn = X + (size_t)(c + 1) * 4096;
#pragma unroll
            for (int q = 0; q < 8; q++) pv[q] = Xn[t + 512 * q];
        }
#pragma unroll
        for (int ks = 0; ks < 8; ks++) {
            u32 aH[4];
            u32 ar = (u32)(ks * 16) + a_radd;
            ldm4t(aH, sSH + phys(ar, a_c));
            u32 br = (u32)(ks * 16) + b_radd;
#pragma unroll
            for (int np = 0; np < 4; np++) {
                u32 bH[4];
                u32 bc = (u32)(nhf * 8 + np * 2) + b_cadd;
                ldm4t(bH, sSH + phys(br, bc));
                mma16816(acc[2 * np],     aH, bH[0], bH[1]);
                mma16816(acc[2 * np + 1], aH, bH[2], bH[3]);
            }
        }
    }
    float* dst = g_gram_part[side][half];
    int r0 = m0 + (lane >> 2);
    int j0 = nhf * 64 + 2 * (lane & 3);
#pragma unroll
    for (int nt = 0; nt < 8; nt++) {
        int j = j0 + 8 * nt;
        *(float2*)&dst[r0 * DD + j]       = make_float2(acc[nt][0], acc[nt][1]);
        *(float2*)&dst[(r0 + 8) * DD + j] = make_float2(acc[nt][2], acc[nt][3]);
    }
}

// ---------------------------------------------------------------------------
// Kernel 2: reduce partials -> bf16 hi image, plus W2 image (merged; W2 has
// no dependency on gram, it just needs to be done before the fused kernel).
// ---------------------------------------------------------------------------
__global__ void reduce_split_kernel(const float* __restrict__ mp_w) {
    int idx = blockIdx.x * blockDim.x + threadIdx.x;
    int s = idx >> 14, e = idx & 16383;
    float v = g_gram_part[s][0][e] + g_gram_part[s][1][e];
    g_gimgH[s][e] = __float2bfloat16(v);
    if (idx < DD * DD) {
        float w = mp_w[idx];
        g_w2H[idx] = __float2bfloat16(w * w);
    }
}

// ---------------------------------------------------------------------------
// Kernel 3: fused  V = Xh·Gh -> in-register E-frags -> match GEMMs.
// 256 threads / 8 warps, warp = one 16-row m-tile covering FULL n/k/p range.
// GEMM1's C-fragment layout == GEMM2's A-fragment layout, so E0/E1/E2
// fragments are built with mul.bf16x2 from packed V (regs) and X (4 scalar
// conflict-free LDS per k-chunk) — E never touches smem.  One __syncthreads
// total; smem = XH + GH + WH = 96 KB -> 2 CTAs/SM.
// ---------------------------------------------------------------------------
#define FUSED_SMEM (3 * 32768)

__global__ void __launch_bounds__(256, 2) fused_kernel(const float* __restrict__ feats,
                                                       float* __restrict__ out) {
    extern __shared__ __align__(16) unsigned char sm[];
    unsigned char* XH = sm;
    unsigned char* BH = sm + 32768;
    unsigned char* WH = sm + 65536;
    u32 sXH = s2u(sm);
    u32 sBH = sXH + 32768;
    u32 sWH = sXH + 65536;

    int blk = blockIdx.x, g = blk >> 4, tile = blk & 15;
    int t = threadIdx.x, wid = t >> 5, lane = t & 31;
    size_t lbase = (size_t)g * LL + (size_t)tile * 128;

    int m0 = wid * 16;

    // ---- stage: X (hi only), G hi (partner), W2 (hi)
    {
        const float4* xs = (const float4*)(feats + lbase * DD);
#pragma unroll
        for (int q = 0; q < 16; q++) {
            int idx = t + 256 * q;
            u32 r = (u32)(idx >> 5);
            u32 ln = (u32)(idx & 31);
            u32 off = phys(r, ln >> 1) + (ln & 1) * 8u;
            float4 v = xs[idx];
            *(uint2*)(XH + off) = make_uint2(pk(v.x, v.y), pk(v.z, v.w));
        }
        const uint4* gh = (const uint4*)&g_gimgH[g ^ 1][0];
        const uint4* wh = (const uint4*)&g_w2H[0];
#pragma unroll
        for (int q = 0; q < 8; q++) {
            int idx = t + 256 * q;
            u32 r = (u32)(idx >> 4), ch = (u32)(idx & 15);
            u32 off = phys(r, ch);
            *(uint4*)(BH + off) = gh[idx];
            *(uint4*)(WH + off) = wh[idx];
        }
    }
    __syncthreads();   // the ONLY block-wide sync

    u32 aA_r = (u32)m0 + (u32)(lane & 15);
    u32 aA_c = (u32)(lane >> 4);
    u32 bB_radd = (u32)((lane & 7) + (lane >> 4) * 8);
    u32 bB_cadd = (u32)((lane >> 3) & 1);

    // ---- GEMM1: V = Xh · Gh, full n = 128 (16 n-tiles per warp)
    float vac[16][4];
#pragma unroll
    for (int i = 0; i < 16; i++) { vac[i][0] = vac[i][1] = vac[i][2] = vac[i][3] = 0.f; }
#pragma unroll
    for (int ks = 0; ks < 8; ks++) {
        u32 aH[4];
        u32 ac = (u32)(ks * 2) + aA_c;
        ldm4(aH, sXH + phys(aA_r, ac));
        u32 bc = (u32)(ks * 2) + bB_cadd;
#pragma unroll
        for (int np = 0; np < 8; np++) {
            u32 br = (u32)(np * 16) + bB_radd;
            u32 bH[4];
            ldm4(bH, sBH + phys(br, bc));
            mma16816(vac[2 * np],     aH, bH[0], bH[1]);
            mma16816(vac[2 * np + 1], aH, bH[2], bH[3]);
        }
    }

    // ---- pack V to bf16 pairs in C-fragment layout (== A-frag layout for GEMM2)
    u32 vpk[32];
#pragma unroll
    for (int nt = 0; nt < 16; nt++) {
        vpk[2 * nt]     = pk(vac[nt][0], vac[nt][1]);
        vpk[2 * nt + 1] = pk(vac[nt][2], vac[nt][3]);
    }

    // ---- GEMM2 (+fused epilogue): 4 passes of 32 perspectives.
    // A-frags per k-chunk ks built in regs: v from vpk[4ks..4ks+3],
    // x from 4 conflict-free LDS.32, E = mul.bf16x2.
    float* outp = out + lbase * DD;
    u32 r0 = (u32)m0 + (u32)(lane >> 2);
    u32 sub = 4u * (u32)(lane & 3);
#pragma unroll 1
    for (int pp = 0; pp < 4; pp++) {
        float aN[4][4], a1[4][4], a2[4][4];
#pragma unroll
        for (int i = 0; i < 4; i++) {
            aN[i][0] = aN[i][1] = aN[i][2] = aN[i][3] = 0.f;
            a1[i][0] = a1[i][1] = a1[i][2] = a1[i][3] = 0.f;
            a2[i][0] = a2[i][1] = a2[i][2] = a2[i][3] = 0.f;
        }
#pragma unroll
        for (int ks = 0; ks < 8; ks++) {
            u32 xp[4];
            xp[0] = *(const u32*)(XH + phys(r0,     (u32)(2 * ks))     + sub);
            xp[1] = *(const u32*)(XH + phys(r0 + 8, (u32)(2 * ks))     + sub);
            xp[2] = *(const u32*)(XH + phys(r0,     (u32)(2 * ks + 1)) + sub);
            xp[3] = *(const u32*)(XH + phys(r0 + 8, (u32)(2 * ks + 1)) + sub);
            u32 e0[4], e1[4], e2[4];
#pragma unroll
            for (int j = 0; j < 4; j++) {
                u32 vp = vpk[4 * ks + j];
                e0[j] = hmul2(xp[j], vp);
                e1[j] = hmul2(xp[j], xp[j]);
                e2[j] = hmul2(vp, vp);
            }
            u32 bc = (u32)(ks * 2) + bB_cadd;
#pragma unroll
            for (int np = 0; np < 2; np++) {
                u32 br = (u32)(pp * 32 + np * 16) + bB_radd;
                u32 wh[4];
                ldm4(wh, sWH + phys(br, bc));
                mma16816(aN[2 * np], e0, wh[0], wh[1]);
                mma16816(a1[2 * np], e1, wh[0], wh[1]);
                mma16816(a2[2 * np], e2, wh[0], wh[1]);
                mma16816(aN[2 * np + 1], e0, wh[2], wh[3]);
                mma16816(a1[2 * np + 1], e1, wh[2], wh[3]);
                mma16816(a2[2 * np + 1], e2, wh[2], wh[3]);
            }
        }
        // epilogue: o = num * rsqrt(max(n1*n2, eps^2))  ==  num / max(sqrt(n1*n2), eps)
#pragma unroll
        for (int nt = 0; nt < 4; nt++) {
            int p0 = pp * 32 + nt * 8 + 2 * (lane & 3);
            float r0f = rsqrtf(fmaxf(a1[nt][0] * a2[nt][0], 1e-16f));
            float r1f = rsqrtf(fmaxf(a1[nt][1] * a2[nt][1], 1e-16f));
            float r2f = rsqrtf(fmaxf(a1[nt][2] * a2[nt][2], 1e-16f));
            float r3f = rsqrtf(fmaxf(a1[nt][3] * a2[nt][3], 1e-16f));
            *(float2*)&outp[(size_t)r0 * DD + p0] =
                make_float2(aN[nt][0] * r0f, aN[nt][1] * r1f);
            *(float2*)&outp[(size_t)(r0 + 8) * DD + p0] =
                make_float2(aN[nt][2] * r2f, aN[nt][3] * r3f);
        }
    }
}

// ---------------------------------------------------------------------------
extern "C" void kernel_launch(void* const* d_in, const int* in_sizes, int n_in,
                              void* d_out, int out_size) {
    const float* feats = (const float*)d_in[0];
    const float* mp_w  = (const float*)d_in[1];
    float* out = (float*)d_out;

    cudaFuncSetAttribute(fused_kernel, cudaFuncAttributeMaxDynamicSharedMemorySize, FUSED_SMEM);

    gram_kernel<<<NG * 2, 512, 32768>>>(feats);
    reduce_split_kernel<<<(NG * DD * DD) / 256, 256>>>(mp_w);
    fused_kernel<<<NG * (LL / 128), 256, FUSED_SMEM>>>(feats, out);
}